// round 1
// baseline (speedup 1.0000x reference)
#include <cuda_runtime.h>

#define CC   256
#define CQ   64
#define NPIX 4096
#define NPAIR 4   // pair p = stream*2 + batch

// Scratch (allocation-free rule: __device__ globals)
__device__ float g_W[2][384][CC];      // stacked [q(64); k(64); v(256)] weights per stream
__device__ float g_Bias[2][384];
__device__ float g_Q[NPAIR][NPIX][CQ]; // Q^T  [n][cq]
__device__ float g_K[NPAIR][NPIX][CQ]; // K^T  [n][cq]
__device__ float g_Vt[NPAIR][NPIX][CC];// V^T  [n][c]

// ---------------------------------------------------------------------------
// Pack per-stream weights into one stacked matrix (makes projection one GEMM)
// ---------------------------------------------------------------------------
__global__ void prep_weights(
    const float* __restrict__ q1w, const float* __restrict__ q1b,
    const float* __restrict__ k1w, const float* __restrict__ k1b,
    const float* __restrict__ v1w, const float* __restrict__ v1b,
    const float* __restrict__ q2w, const float* __restrict__ q2b,
    const float* __restrict__ k2w, const float* __restrict__ k2b,
    const float* __restrict__ v2w, const float* __restrict__ v2b)
{
    int o = blockIdx.x;   // 0..383
    int s = blockIdx.y;   // 0..1
    const float* w; const float* bsrc; int row;
    if (o < 64)       { w = s ? q2w : q1w; bsrc = s ? q2b : q1b; row = o; }
    else if (o < 128) { w = s ? k2w : k1w; bsrc = s ? k2b : k1b; row = o - 64; }
    else              { w = s ? v2w : v1w; bsrc = s ? v2b : v1b; row = o - 128; }
    g_W[s][o][threadIdx.x] = w[row * CC + threadIdx.x];
    if (threadIdx.x == 0) g_Bias[s][o] = bsrc[row];
}

// ---------------------------------------------------------------------------
// Projection GEMM: Y[384, N] = W_s[384,256] @ X[256, N] (+bias), scatter into
// g_Q / g_K / g_Vt in transposed (n-major) layouts for the flash kernel.
// 64x64 block tile, 256 threads, 4x4 micro-tile.
// ---------------------------------------------------------------------------
__global__ __launch_bounds__(256) void proj_gemm(
    const float* __restrict__ in1, const float* __restrict__ in2)
{
    int p = blockIdx.z; int s = p >> 1, b = p & 1;
    const float* x = (s ? in2 : in1) + (size_t)b * CC * NPIX;  // [C][N]
    int o0 = blockIdx.y * 64;
    int n0 = blockIdx.x * 64;
    __shared__ float As[16][68];   // [k][o]
    __shared__ float Bs[16][68];   // [k][n]
    int tid = threadIdx.x;
    int ty = tid >> 4, tx = tid & 15;
    int lo = tid >> 2, lk = (tid & 3) << 2;     // A-load mapping
    int bk = tid >> 4, bn = (tid & 15) << 2;    // B-load mapping
    float acc[4][4] = {};
    for (int kc = 0; kc < CC; kc += 16) {
        float4 wv = *(const float4*)&g_W[s][o0 + lo][kc + lk];
        float4 xv = *(const float4*)&x[(size_t)(kc + bk) * NPIX + n0 + bn];
        As[lk + 0][lo] = wv.x; As[lk + 1][lo] = wv.y;
        As[lk + 2][lo] = wv.z; As[lk + 3][lo] = wv.w;
        *(float4*)&Bs[bk][bn] = xv;
        __syncthreads();
        #pragma unroll
        for (int k = 0; k < 16; k++) {
            float a[4], bb[4];
            #pragma unroll
            for (int i = 0; i < 4; i++) a[i] = As[k][ty * 4 + i];
            #pragma unroll
            for (int j = 0; j < 4; j++) bb[j] = Bs[k][tx * 4 + j];
            #pragma unroll
            for (int i = 0; i < 4; i++)
                #pragma unroll
                for (int j = 0; j < 4; j++)
                    acc[i][j] = fmaf(a[i], bb[j], acc[i][j]);
        }
        __syncthreads();
    }
    #pragma unroll
    for (int i = 0; i < 4; i++) {
        int og = o0 + ty * 4 + i;
        float bias = g_Bias[s][og];
        #pragma unroll
        for (int j = 0; j < 4; j++) {
            int n = n0 + tx * 4 + j;
            float v = acc[i][j] + bias;
            if (og < 64)        g_Q[p][n][og] = v;
            else if (og < 128)  g_K[p][n][og - 64] = v;
            else                g_Vt[p][n][og - 128] = v;
        }
    }
}

// ---------------------------------------------------------------------------
// Flash attention: per (pair, 128-row block). Online softmax, O in registers.
// 512 threads. S: 4x4 micro over [128x64]; PV: 8x8 micro over [128x256].
// ---------------------------------------------------------------------------
__global__ __launch_bounds__(512) void flash_attn(
    const float* __restrict__ in1, const float* __restrict__ in2,
    const float* __restrict__ gamma, float* __restrict__ out)
{
    extern __shared__ float sm[];
    float* Qs  = sm;                    // 128 x 65
    float* Ks  = Qs + 128 * 65;         // 64 x 65
    float* Pts = Ks + 64 * 65;          // 64 x 132  (stores S^T then P^T)
    float* Vts = Pts + 64 * 132;        // 64 x 260
    float* mrow = Vts + 64 * 260;       // 128
    float* lrow = mrow + 128;           // 128
    float* arow = lrow + 128;           // 128

    int p = blockIdx.y; int s = p >> 1, b = p & 1;
    int i0 = blockIdx.x * 128;
    int tid = threadIdx.x;

    // load Q block [128 x 64]
    for (int t = tid; t < 2048; t += 512) {
        int r = t >> 4, q = (t & 15) << 2;
        float4 v = *(const float4*)&g_Q[p][i0 + r][q];
        float* d = &Qs[r * 65 + q];
        d[0] = v.x; d[1] = v.y; d[2] = v.z; d[3] = v.w;
    }
    if (tid < 128) { mrow[tid] = -1e30f; lrow[tid] = 0.f; }

    float acc[8][8] = {};
    int rg  = tid >> 5, cg  = tid & 31;  int r0p = rg << 3, c0 = cg << 3;  // PV map
    int rgs = tid >> 4, jgs = tid & 15;  int r0s = rgs << 2, j0s = jgs << 2; // S map
    int rsm = tid >> 2, part = tid & 3;                                     // softmax map

    __syncthreads();

    for (int jt = 0; jt < 64; jt++) {
        int j0 = jt << 6;
        // load K tile [64 x 64]
        for (int t = tid; t < 1024; t += 512) {
            int j = t >> 4, q = (t & 15) << 2;
            float4 v = *(const float4*)&g_K[p][j0 + j][q];
            float* d = &Ks[j * 65 + q];
            d[0] = v.x; d[1] = v.y; d[2] = v.z; d[3] = v.w;
        }
        // load V^T tile [64 x 256]
        for (int t = tid; t < 4096; t += 512) {
            int j = t >> 6, q = (t & 63) << 2;
            *(float4*)&Vts[j * 260 + q] = *(const float4*)&g_Vt[p][j0 + j][q];
        }
        __syncthreads();

        // --- S = Q K^T  (write transposed: Pts[j][r]) ---
        float sv[4][4] = {};
        #pragma unroll 8
        for (int k = 0; k < 64; k++) {
            float a[4], kk[4];
            #pragma unroll
            for (int i = 0; i < 4; i++) a[i]  = Qs[(r0s + i) * 65 + k];
            #pragma unroll
            for (int j = 0; j < 4; j++) kk[j] = Ks[(j0s + j) * 65 + k];
            #pragma unroll
            for (int i = 0; i < 4; i++)
                #pragma unroll
                for (int j = 0; j < 4; j++)
                    sv[i][j] = fmaf(a[i], kk[j], sv[i][j]);
        }
        #pragma unroll
        for (int j = 0; j < 4; j++)
            #pragma unroll
            for (int i = 0; i < 4; i++)
                Pts[(j0s + j) * 132 + r0s + i] = sv[i][j];
        __syncthreads();

        // --- online softmax (4 threads per row, same warp) ---
        int jb = part << 4;
        float mloc = -1e30f;
        #pragma unroll
        for (int j = 0; j < 16; j++) mloc = fmaxf(mloc, Pts[(jb + j) * 132 + rsm]);
        mloc = fmaxf(mloc, __shfl_xor_sync(0xffffffffu, mloc, 1));
        mloc = fmaxf(mloc, __shfl_xor_sync(0xffffffffu, mloc, 2));
        float mold = mrow[rsm];
        float mnew = fmaxf(mold, mloc);
        float ssum = 0.f;
        #pragma unroll
        for (int j = 0; j < 16; j++) {
            float e = __expf(Pts[(jb + j) * 132 + rsm] - mnew);
            Pts[(jb + j) * 132 + rsm] = e;
            ssum += e;
        }
        ssum += __shfl_xor_sync(0xffffffffu, ssum, 1);
        ssum += __shfl_xor_sync(0xffffffffu, ssum, 2);
        if (part == 0) {
            float al = __expf(mold - mnew);
            mrow[rsm] = mnew;
            lrow[rsm] = lrow[rsm] * al + ssum;
            arow[rsm] = al;
        }
        __syncthreads();

        // --- O = diag(alpha)*O + P V^T ---
        #pragma unroll
        for (int i = 0; i < 8; i++) {
            float al = arow[r0p + i];
            #pragma unroll
            for (int c = 0; c < 8; c++) acc[i][c] *= al;
        }
        #pragma unroll 4
        for (int j = 0; j < 64; j++) {
            float4 p0 = *(const float4*)&Pts[j * 132 + r0p];
            float4 p1 = *(const float4*)&Pts[j * 132 + r0p + 4];
            float4 v0 = *(const float4*)&Vts[j * 260 + c0];
            float4 v1 = *(const float4*)&Vts[j * 260 + c0 + 4];
            float pr[8] = {p0.x, p0.y, p0.z, p0.w, p1.x, p1.y, p1.z, p1.w};
            float vv[8] = {v0.x, v0.y, v0.z, v0.w, v1.x, v1.y, v1.z, v1.w};
            #pragma unroll
            for (int i = 0; i < 8; i++)
                #pragma unroll
                for (int c = 0; c < 8; c++)
                    acc[i][c] = fmaf(pr[i], vv[c], acc[i][c]);
        }
        __syncthreads();
    }

    // epilogue: out = gamma * O / l + input
    float gm = gamma[0];
    const float* xin = (s ? in2 : in1) + (size_t)b * CC * NPIX;
    float* o = out + (size_t)p * CC * NPIX;   // [s][b][c][n], p = s*2+b
    #pragma unroll
    for (int i = 0; i < 8; i++) {
        int r = i0 + r0p + i;
        float inv = 1.f / lrow[r0p + i];
        #pragma unroll
        for (int c = 0; c < 8; c++) {
            int cc = c0 + c;
            o[(size_t)cc * NPIX + r] = gm * acc[i][c] * inv + xin[(size_t)cc * NPIX + r];
        }
    }
}

// ---------------------------------------------------------------------------
extern "C" void kernel_launch(void* const* d_in, const int* in_sizes, int n_in,
                              void* d_out, int out_size)
{
    const float* in1 = (const float*)d_in[0];
    const float* in2 = (const float*)d_in[1];
    const float* q1w = (const float*)d_in[2];  const float* q1b = (const float*)d_in[3];
    const float* k1w = (const float*)d_in[4];  const float* k1b = (const float*)d_in[5];
    const float* v1w = (const float*)d_in[6];  const float* v1b = (const float*)d_in[7];
    const float* q2w = (const float*)d_in[8];  const float* q2b = (const float*)d_in[9];
    const float* k2w = (const float*)d_in[10]; const float* k2b = (const float*)d_in[11];
    const float* v2w = (const float*)d_in[12]; const float* v2b = (const float*)d_in[13];
    // d_in[14..21]: gate branch — mathematically cancels in softmax, unused.
    const float* gamma = (const float*)d_in[22];
    float* out = (float*)d_out;

    prep_weights<<<dim3(384, 2), 256>>>(q1w, q1b, k1w, k1b, v1w, v1b,
                                        q2w, q2b, k2w, k2b, v2w, v2b);
    proj_gemm<<<dim3(64, 6, 4), 256>>>(in1, in2);

    size_t smem = (size_t)(128 * 65 + 64 * 65 + 64 * 132 + 64 * 260 + 3 * 128) * sizeof(float);
    cudaFuncSetAttribute(flash_attn, cudaFuncAttributeMaxDynamicSharedMemorySize, (int)smem);
    flash_attn<<<dim3(32, 4), 512, smem>>>(in1, in2, gamma, out);
}